// round 10
// baseline (speedup 1.0000x reference)
#include <cuda_runtime.h>
#include <cuda_fp16.h>
#include <math.h>
#include <stdint.h>

#define B_ 4
#define T_ 1024
#define D_ 1024
#define H_ 16
#define DH_ 64
#define E_ 8
#define FF_ 4096
#define BT_ (B_*T_)
#define NASSIGN (BT_*2)

// ---------------- scratch ----------------
__device__ __half g_h16h[BT_ * D_];
__device__ __half g_h16l[BT_ * D_];
__device__ __half g_qkvh[BT_ * 3 * D_];
__device__ __half g_qkvl[BT_ * 3 * D_];
__device__ __half g_oh[BT_ * D_];
__device__ __half g_ol[BT_ * D_];
__device__ float  g_x1[BT_ * D_];
__device__ __half g_x2h[BT_ * D_];
__device__ __half g_wqkvh[3 * D_ * D_];
__device__ __half g_wqkvl[3 * D_ * D_];
__device__ __half g_wprojh[D_ * D_];
__device__ __half g_wprojl[D_ * D_];
__device__ __half g_hid[(size_t)NASSIGN * FF_];
__device__ float  g_contrib[NASSIGN * D_];
__device__ int    g_count[E_];
__device__ int    g_assign[E_ * BT_];
__device__ float  g_wt[NASSIGN];

__device__ __forceinline__ float gelu_exact(float x) {
    return 0.5f * x * (1.0f + erff(x * 0.70710678118654752440f));
}
__device__ __forceinline__ uint32_t smem_u32(const void* p) {
    uint32_t a;
    asm("{ .reg .u64 t; cvta.to.shared.u64 t, %1; cvt.u32.u64 %0, t; }" : "=r"(a) : "l"(p));
    return a;
}
__device__ __forceinline__ void ldmx4(uint32_t* r, uint32_t addr) {
    asm volatile("ldmatrix.sync.aligned.m8n8.x4.shared.b16 {%0,%1,%2,%3}, [%4];"
        : "=r"(r[0]), "=r"(r[1]), "=r"(r[2]), "=r"(r[3]) : "r"(addr));
}
__device__ __forceinline__ void ldmx4t(uint32_t* r, uint32_t addr) {
    asm volatile("ldmatrix.sync.aligned.m8n8.x4.trans.shared.b16 {%0,%1,%2,%3}, [%4];"
        : "=r"(r[0]), "=r"(r[1]), "=r"(r[2]), "=r"(r[3]) : "r"(addr));
}
__device__ __forceinline__ void mma16816(float* c, const uint32_t* a, uint32_t b0, uint32_t b1) {
    asm volatile(
        "mma.sync.aligned.m16n8k16.row.col.f32.f16.f16.f32 "
        "{%0,%1,%2,%3}, {%4,%5,%6,%7}, {%8,%9}, {%0,%1,%2,%3};"
        : "+f"(c[0]), "+f"(c[1]), "+f"(c[2]), "+f"(c[3])
        : "r"(a[0]), "r"(a[1]), "r"(a[2]), "r"(a[3]), "r"(b0), "r"(b1));
}
__device__ __forceinline__ void packsplit(uint32_t& h, uint32_t& l, float x, float y) {
    __half hx = __float2half_rn(x), hy = __float2half_rn(y);
    __half lx = __float2half_rn(x - __half2float(hx));
    __half ly = __float2half_rn(y - __half2float(hy));
    __half2 hh; hh.x = hx; hh.y = hy; h = *(uint32_t*)&hh;
    __half2 ll; ll.x = lx; ll.y = ly; l = *(uint32_t*)&ll;
}
__device__ __forceinline__ uint4 cvt8f(const float4& a, const float4& b) {
    __half2 h0 = __floats2half2_rn(a.x, a.y);
    __half2 h1 = __floats2half2_rn(a.z, a.w);
    __half2 h2 = __floats2half2_rn(b.x, b.y);
    __half2 h3 = __floats2half2_rn(b.z, b.w);
    uint4 o;
    o.x = *(uint32_t*)&h0; o.y = *(uint32_t*)&h1;
    o.z = *(uint32_t*)&h2; o.w = *(uint32_t*)&h3;
    return o;
}

// ---------------- weight convert (qkv/proj only) ----------------
__global__ void __launch_bounds__(256) convk(
    const float* __restrict__ in, __half* __restrict__ oh, __half* __restrict__ ol)
{
    size_t i = ((size_t)blockIdx.x * 256 + threadIdx.x) * 4;
    float4 v = *(const float4*)(in + i);
    __half2 h0 = __floats2half2_rn(v.x, v.y);
    __half2 h1 = __floats2half2_rn(v.z, v.w);
    *(__half2*)(oh + i) = h0; *(__half2*)(oh + i + 2) = h1;
    float2 f0 = __half22float2(h0), f1 = __half22float2(h1);
    *(__half2*)(ol + i) = __floats2half2_rn(v.x - f0.x, v.y - f0.y);
    *(__half2*)(ol + i + 2) = __floats2half2_rn(v.z - f1.x, v.w - f1.y);
}

// =====================================================================
// HMMA GEMM. 128x128 tile, BK=32, 8 warps, reg-staged double buffer.
// GM: 0=dense, 1=gather token(slot>>1), 2=gather slot.
// EM: 0=qkv hi/lo fp16, 1=f32 + residual, 2=gelu->fp16, 3=*wt->f32.
// SPLIT: fp16 hi/lo 3-pass. BF32: B source is fp32 (convert in sts).
// =====================================================================
template<int GM, int EM, bool SPLIT, bool BF32>
__global__ void __launch_bounds__(256, 1) tgemm(
    const __half* __restrict__ Ah, const __half* __restrict__ Al,
    const __half* __restrict__ Bh, const __half* __restrict__ Bl,
    const float* __restrict__ Bf,
    void* __restrict__ Cv, __half* __restrict__ Cv2, const float* __restrict__ Rv,
    const int* __restrict__ cnt, const int* __restrict__ assign,
    const float* __restrict__ wt,
    int Mdense, int K, int lda, int ldb, int ldc, size_t strideB)
{
    extern __shared__ char smem[];
    __shared__ int slist[128];
    constexpr int TILE = 10240;
    constexpr int NT = SPLIT ? 4 : 2;
    constexpr int STAGE = NT * TILE;

    int tid = threadIdx.x, lane = tid & 31, warp = tid >> 5;
    int m0 = blockIdx.y * 128, n0 = blockIdx.x * 128;

    int Mlim = Mdense;
    if (GM != 0) {
        int e = blockIdx.z;
        Mlim = cnt[e];
        if (m0 >= Mlim) return;
        const int* lst = assign + e * BT_;
        if (BF32) Bf = Bf + (size_t)e * strideB;
        else      Bh = Bh + (size_t)e * strideB;
        if (tid < 128) {
            int idx = m0 + tid;
            if (idx > Mlim - 1) idx = Mlim - 1;
            slist[tid] = lst[idx];
        }
        __syncthreads();
    }
    uint32_t sb = smem_u32(smem);

    int ca = tid & 3;
    size_t aoffg[2], boffg[2];
#pragma unroll
    for (int i = 0; i < 2; ++i) {
        int r = (tid >> 2) + i * 64;
        int src;
        if (GM == 0)      src = m0 + r;
        else if (GM == 1) src = slist[r] >> 1;
        else              src = slist[r];
        aoffg[i] = (size_t)src * lda + ca * 8;
        boffg[i] = (size_t)(n0 + r) * ldb + ca * 8;
    }

    uint4 arH[2], arL[2], brH[2], brL[2];
    float4 brF[2][2];
    auto ldg = [&](int kc) {
        int k0 = kc * 32;
#pragma unroll
        for (int i = 0; i < 2; ++i) {
            arH[i] = *(const uint4*)(Ah + aoffg[i] + k0);
            if (BF32) {
                brF[i][0] = *(const float4*)(Bf + boffg[i] + k0);
                brF[i][1] = *(const float4*)(Bf + boffg[i] + k0 + 4);
            } else {
                brH[i] = *(const uint4*)(Bh + boffg[i] + k0);
            }
            if (SPLIT) {
                arL[i] = *(const uint4*)(Al + aoffg[i] + k0);
                brL[i] = *(const uint4*)(Bl + boffg[i] + k0);
            }
        }
    };
    auto sts = [&](int stg) {
        char* base = smem + stg * STAGE;
#pragma unroll
        for (int i = 0; i < 2; ++i) {
            int r = (tid >> 2) + i * 64;
            int off = r * 80 + ca * 16;
            *(uint4*)(base + off) = arH[i];
            uint4 bv = BF32 ? cvt8f(brF[i][0], brF[i][1]) : brH[i];
            *(uint4*)(base + (SPLIT ? 2 : 1) * TILE + off) = bv;
            if (SPLIT) {
                *(uint4*)(base + TILE + off) = arL[i];
                *(uint4*)(base + 3 * TILE + off) = brL[i];
            }
        }
    };

    float acc[4][4][4];
#pragma unroll
    for (int i = 0; i < 4; ++i)
#pragma unroll
        for (int j = 0; j < 4; ++j)
#pragma unroll
            for (int k = 0; k < 4; ++k) acc[i][j][k] = 0.f;

    int wm = (warp >> 2) * 64, wn = (warp & 3) * 32;
    uint32_t frag_off = (uint32_t)((lane & 15) * 80 + (lane >> 4) * 16);

    auto compute = [&](int stg) {
        uint32_t base = sb + stg * STAGE;
        uint32_t AhS = base;
        uint32_t AlS = base + TILE;
        uint32_t BhS = base + (SPLIT ? 2 : 1) * TILE;
        uint32_t BlS = BhS + TILE;
#pragma unroll
        for (int ks = 0; ks < 2; ++ks) {
            uint32_t ko = ks * 32;
            uint32_t ah[4][4], bh[2][4];
#pragma unroll
            for (int mf = 0; mf < 4; ++mf)
                ldmx4(ah[mf], AhS + (wm + mf * 16) * 80 + frag_off + ko);
#pragma unroll
            for (int np = 0; np < 2; ++np)
                ldmx4(bh[np], BhS + (wn + np * 16) * 80 + frag_off + ko);
            if (!SPLIT) {
#pragma unroll
                for (int mf = 0; mf < 4; ++mf)
#pragma unroll
                    for (int nf = 0; nf < 4; ++nf) {
                        int np = nf >> 1, u = nf & 1;
                        mma16816(acc[mf][nf], ah[mf], bh[np][u], bh[np][u + 2]);
                    }
            } else {
                uint32_t al[4][4], bl[2][4];
#pragma unroll
                for (int mf = 0; mf < 4; ++mf)
                    ldmx4(al[mf], AlS + (wm + mf * 16) * 80 + frag_off + ko);
#pragma unroll
                for (int np = 0; np < 2; ++np)
                    ldmx4(bl[np], BlS + (wn + np * 16) * 80 + frag_off + ko);
#pragma unroll
                for (int mf = 0; mf < 4; ++mf)
#pragma unroll
                    for (int nf = 0; nf < 4; ++nf) {
                        int np = nf >> 1, u = nf & 1;
                        mma16816(acc[mf][nf], ah[mf], bh[np][u], bh[np][u + 2]);
                        mma16816(acc[mf][nf], ah[mf], bl[np][u], bl[np][u + 2]);
                        mma16816(acc[mf][nf], al[mf], bh[np][u], bh[np][u + 2]);
                    }
            }
        }
    };

    const int NC = K / 32;
    ldg(0); sts(0); __syncthreads();
    for (int c = 0; c < NC; ++c) {
        if (c + 1 < NC) ldg(c + 1);
        compute(c & 1);
        if (c + 1 < NC) sts((c + 1) & 1);
        __syncthreads();
    }

#pragma unroll
    for (int mf = 0; mf < 4; ++mf) {
#pragma unroll
        for (int nf = 0; nf < 4; ++nf) {
            int r0 = wm + mf * 16 + (lane >> 2);
            int gc = n0 + wn + nf * 8 + (lane & 3) * 2;
            float* cc = acc[mf][nf];
#pragma unroll
            for (int hf = 0; hf < 2; ++hf) {
                int rl = r0 + hf * 8;
                float v0 = cc[hf * 2], v1 = cc[hf * 2 + 1];
                if (GM == 0 || (m0 + rl) < Mlim) {
                    if (EM == 0) {
                        uint32_t hh, ll;
                        packsplit(hh, ll, v0, v1);
                        size_t idx = (size_t)(m0 + rl) * ldc + gc;
                        *(uint32_t*)((__half*)Cv + idx) = hh;
                        *(uint32_t*)(Cv2 + idx) = ll;
                    } else if (EM == 1) {
                        const float* R = Rv + (size_t)(m0 + rl) * ldc + gc;
                        float2 st; st.x = v0 + R[0]; st.y = v1 + R[1];
                        *(float2*)((float*)Cv + (size_t)(m0 + rl) * ldc + gc) = st;
                    } else if (EM == 2) {
                        int a = slist[rl];
                        __half2 hh = __floats2half2_rn(gelu_exact(v0), gelu_exact(v1));
                        *(__half2*)((__half*)Cv + (size_t)a * ldc + gc) = hh;
                    } else {
                        int a = slist[rl];
                        float wv = wt[a];
                        float2 st; st.x = wv * v0; st.y = wv * v1;
                        *(float2*)((float*)Cv + (size_t)a * ldc + gc) = st;
                    }
                }
            }
        }
    }
}

// =====================================================================
// HMMA flash attention (R7 version): fp16 hi/lo split QK and PV.
// 128 q-rows/block, 8 warps x 16 rows, 64-key tiles, causal, stride 144.
// =====================================================================
__global__ void __launch_bounds__(256, 1) attn_hmma(
    const __half* __restrict__ qh, const __half* __restrict__ ql,
    __half* __restrict__ Oh, __half* __restrict__ Ol)
{
    extern __shared__ char sm[];
    const int QH = 0, QL = 18432, KH = 36864, KL = 46080, VH = 55296, VL = 64512;
    int bh = blockIdx.y;
    int b = bh >> 4, h = bh & 15;
    int q0 = blockIdx.x * 128;
    int tid = threadIdx.x, lane = tid & 31, warp = tid >> 5;
    uint32_t sb = smem_u32(sm);
    size_t base3d = (size_t)(b * T_) * 3 * D_ + h * 64;

#pragma unroll
    for (int i = 0; i < 4; ++i) {
        int q = tid + i * 256; int r = q >> 3, c = q & 7;
        size_t g = base3d + (size_t)(q0 + r) * 3 * D_ + c * 8;
        *(uint4*)(sm + QH + r * 144 + c * 16) = *(const uint4*)(qh + g);
        *(uint4*)(sm + QL + r * 144 + c * 16) = *(const uint4*)(ql + g);
    }

    float Oacc[8][4];
#pragma unroll
    for (int i = 0; i < 8; ++i)
#pragma unroll
        for (int j = 0; j < 4; ++j) Oacc[i][j] = 0.f;
    float m_i[2] = { -1e30f, -1e30f }, l_i[2] = { 0.f, 0.f };

    int wm = warp * 16;
    uint32_t frag_off = (uint32_t)((lane & 15) * 144 + (lane >> 4) * 16);
    int nkt = q0 / 64 + 2;
    __syncthreads();

    for (int kt = 0; kt < nkt; ++kt) {
        int k0 = kt * 64;
#pragma unroll
        for (int i = 0; i < 2; ++i) {
            int q = tid + i * 256; int r = q >> 3, c = q & 7;
            size_t g = base3d + (size_t)(k0 + r) * 3 * D_ + c * 8;
            int off = r * 144 + c * 16;
            *(uint4*)(sm + KH + off) = *(const uint4*)(qh + g + D_);
            *(uint4*)(sm + KL + off) = *(const uint4*)(ql + g + D_);
            *(uint4*)(sm + VH + off) = *(const uint4*)(qh + g + 2 * D_);
            *(uint4*)(sm + VL + off) = *(const uint4*)(ql + g + 2 * D_);
        }
        __syncthreads();

        if (k0 <= q0 + wm + 15) {
            float S[8][4];
#pragma unroll
            for (int i = 0; i < 8; ++i)
#pragma unroll
                for (int j = 0; j < 4; ++j) S[i][j] = 0.f;
#pragma unroll
            for (int kc = 0; kc < 4; ++kc) {
                uint32_t ko = kc * 32;
                uint32_t aH[4], aL[4];
                ldmx4(aH, sb + QH + wm * 144 + frag_off + ko);
                ldmx4(aL, sb + QL + wm * 144 + frag_off + ko);
#pragma unroll
                for (int np = 0; np < 4; ++np) {
                    uint32_t bH[4], bL[4];
                    ldmx4(bH, sb + KH + np * 16 * 144 + frag_off + ko);
                    ldmx4(bL, sb + KL + np * 16 * 144 + frag_off + ko);
#pragma unroll
                    for (int u = 0; u < 2; ++u) {
                        int nf = np * 2 + u;
                        mma16816(S[nf], aH, bH[u], bH[u + 2]);
                        mma16816(S[nf], aH, bL[u], bL[u + 2]);
                        mma16816(S[nf], aL, bH[u], bH[u + 2]);
                    }
                }
            }
            int qg0 = q0 + wm + (lane >> 2);
            int qg1 = qg0 + 8;
            bool dm = (k0 + 63) > (q0 + wm);
            float mx0 = -1e30f, mx1 = -1e30f;
#pragma unroll
            for (int nf = 0; nf < 8; ++nf) {
                int kg = k0 + nf * 8 + (lane & 3) * 2;
                float* s = S[nf];
                s[0] *= 0.125f; s[1] *= 0.125f; s[2] *= 0.125f; s[3] *= 0.125f;
                if (dm) {
                    if (kg > qg0)     s[0] = -1e30f;
                    if (kg + 1 > qg0) s[1] = -1e30f;
                    if (kg > qg1)     s[2] = -1e30f;
                    if (kg + 1 > qg1) s[3] = -1e30f;
                }
                mx0 = fmaxf(mx0, fmaxf(s[0], s[1]));
                mx1 = fmaxf(mx1, fmaxf(s[2], s[3]));
            }
            mx0 = fmaxf(mx0, __shfl_xor_sync(0xffffffffu, mx0, 1));
            mx0 = fmaxf(mx0, __shfl_xor_sync(0xffffffffu, mx0, 2));
            mx1 = fmaxf(mx1, __shfl_xor_sync(0xffffffffu, mx1, 1));
            mx1 = fmaxf(mx1, __shfl_xor_sync(0xffffffffu, mx1, 2));
            float mn0 = fmaxf(m_i[0], mx0), mn1 = fmaxf(m_i[1], mx1);
            float a0 = expf(m_i[0] - mn0), a1 = expf(m_i[1] - mn1);
            float rs0 = 0.f, rs1 = 0.f;
#pragma unroll
            for (int nf = 0; nf < 8; ++nf) {
                float* s = S[nf];
                s[0] = expf(s[0] - mn0); s[1] = expf(s[1] - mn0);
                s[2] = expf(s[2] - mn1); s[3] = expf(s[3] - mn1);
                rs0 += s[0] + s[1]; rs1 += s[2] + s[3];
            }
            rs0 += __shfl_xor_sync(0xffffffffu, rs0, 1);
            rs0 += __shfl_xor_sync(0xffffffffu, rs0, 2);
            rs1 += __shfl_xor_sync(0xffffffffu, rs1, 1);
            rs1 += __shfl_xor_sync(0xffffffffu, rs1, 2);
            l_i[0] = l_i[0] * a0 + rs0;
            l_i[1] = l_i[1] * a1 + rs1;
            m_i[0] = mn0; m_i[1] = mn1;
#pragma unroll
            for (int nf = 0; nf < 8; ++nf) {
                Oacc[nf][0] *= a0; Oacc[nf][1] *= a0;
                Oacc[nf][2] *= a1; Oacc[nf][3] *= a1;
            }
#pragma unroll
            for (int kc = 0; kc < 4; ++kc) {
                uint32_t pH[4], pL[4];
                float* sA = S[2 * kc]; float* sB = S[2 * kc + 1];
                packsplit(pH[0], pL[0], sA[0], sA[1]);
                packsplit(pH[1], pL[1], sA[2], sA[3]);
                packsplit(pH[2], pL[2], sB[0], sB[1]);
                packsplit(pH[3], pL[3], sB[2], sB[3]);
                uint32_t vaddr = (uint32_t)((kc * 16 + (lane & 7) + ((lane >> 4) & 1) * 8) * 144
                                            + ((lane >> 3) & 1) * 16);
#pragma unroll
                for (int g = 0; g < 4; ++g) {
                    uint32_t vH[4], vL[4];
                    ldmx4t(vH, sb + VH + vaddr + g * 32);
                    ldmx4t(vL, sb + VL + vaddr + g * 32);
                    mma16816(Oacc[g * 2], pH, vH[0], vH[2]);
                    mma16816(Oacc[g * 2], pH, vL[0], vL[2]);
                    mma16816(Oacc[g * 2], pL, vH[0], vH[2]);
                    mma16816(Oacc[g * 2 + 1], pH, vH[1], vH[3]);
                    mma16816(Oacc[g * 2 + 1], pH, vL[1], vL[3]);
                    mma16816(Oacc[g * 2 + 1], pL, vH[1], vH[3]);
                }
            }
        }
        __syncthreads();
    }

    float inv0 = 1.0f / l_i[0], inv1 = 1.0f / l_i[1];
    int r0g = b * T_ + q0 + wm + (lane >> 2);
#pragma unroll
    for (int nf = 0; nf < 8; ++nf) {
        int col = h * 64 + nf * 8 + (lane & 3) * 2;
        uint32_t hh, ll;
        packsplit(hh, ll, Oacc[nf][0] * inv0, Oacc[nf][1] * inv0);
        size_t i0 = (size_t)r0g * D_ + col;
        *(uint32_t*)(Oh + i0) = hh;
        *(uint32_t*)(Ol + i0) = ll;
        packsplit(hh, ll, Oacc[nf][2] * inv1, Oacc[nf][3] * inv1);
        size_t i1 = (size_t)(r0g + 8) * D_ + col;
        *(uint32_t*)(Oh + i1) = hh;
        *(uint32_t*)(Ol + i1) = ll;
    }
}

__global__ void zero_counts_kernel(int* cnt) {
    if (threadIdx.x < E_) cnt[threadIdx.x] = 0;
}

// ln1 -> fp16 hi/lo (with cond)
__global__ void __launch_bounds__(256) ln1_kernel(
    const float* __restrict__ x, const float* __restrict__ w,
    const float* __restrict__ c, __half* __restrict__ outh, __half* __restrict__ outl)
{
    int t = blockIdx.x;
    int b = t / T_;
    int tid = threadIdx.x;
    const float* xr = x + (size_t)t * D_;
    float lv[4];
    float s = 0.f, ss = 0.f;
#pragma unroll
    for (int i = 0; i < 4; ++i) {
        lv[i] = xr[tid + i * 256];
        s += lv[i]; ss += lv[i] * lv[i];
    }
    __shared__ float red0[8], red1[8];
#pragma unroll
    for (int o = 16; o; o >>= 1) {
        s  += __shfl_xor_sync(0xffffffffu, s, o);
        ss += __shfl_xor_sync(0xffffffffu, ss, o);
    }
    if ((tid & 31) == 0) { red0[tid >> 5] = s; red1[tid >> 5] = ss; }
    __syncthreads();
    if (tid < 32) {
        s  = (tid < 8) ? red0[tid] : 0.f;
        ss = (tid < 8) ? red1[tid] : 0.f;
#pragma unroll
        for (int o = 4; o; o >>= 1) {
            s  += __shfl_xor_sync(0xffffffffu, s, o);
            ss += __shfl_xor_sync(0xffffffffu, ss, o);
        }
        if (tid == 0) { red0[0] = s; red1[0] = ss; }
    }
    __syncthreads();
    float mu  = red0[0] * (1.0f / D_);
    float var = red1[0] * (1.0f / D_) - mu * mu;
    float inv = rsqrtf(var + 1e-5f);
#pragma unroll
    for (int i = 0; i < 4; ++i) {
        int d = tid + i * 256;
        float v = (lv[i] - mu) * inv * w[d] + c[(size_t)b * D_ + d];
        size_t idx = (size_t)t * D_ + d;
        __half hh = __float2half_rn(v);
        outh[idx] = hh;
        outl[idx] = __float2half_rn(v - __half2float(hh));
    }
}

// fused ln2 + router: LN -> out fp32 + fp16, then top-2 routing from smem
__global__ void __launch_bounds__(256) ln2_router_kernel(
    const float* __restrict__ x, const float* __restrict__ w,
    float* __restrict__ outf, __half* __restrict__ outh,
    const float* __restrict__ RW,
    int* __restrict__ cnt, int* __restrict__ assign, float* __restrict__ wt)
{
    int t = blockIdx.x;
    int tid = threadIdx.x;
    const float* xr = x + (size_t)t * D_;
    __shared__ float xs[D_];
    __shared__ float red0[8], red1[8], lg[E_];
    float lv[4];
    float s = 0.f, ss = 0.f;
#pragma unroll
    for (int i = 0; i < 4; ++i) {
        lv[i] = xr[tid + i * 256];
        s += lv[i]; ss += lv[i] * lv[i];
    }
#pragma unroll
    for (int o = 16; o; o >>= 1) {
        s  += __shfl_xor_sync(0xffffffffu, s, o);
        ss += __shfl_xor_sync(0xffffffffu, ss, o);
    }
    if ((tid & 31) == 0) { red0[tid >> 5] = s; red1[tid >> 5] = ss; }
    __syncthreads();
    if (tid < 32) {
        s  = (tid < 8) ? red0[tid] : 0.f;
        ss = (tid < 8) ? red1[tid] : 0.f;
#pragma unroll
        for (int o = 4; o; o >>= 1) {
            s  += __shfl_xor_sync(0xffffffffu, s, o);
            ss += __shfl_xor_sync(0xffffffffu, ss, o);
        }
        if (tid == 0) { red0[0] = s; red1[0] = ss; }
    }
    __syncthreads();
    float mu  = red0[0] * (1.0f / D_);
    float var = red1[0] * (1.0f / D_) - mu * mu;
    float inv = rsqrtf(var + 1e-5f);
#pragma unroll
    for (int i = 0; i < 4; ++i) {
        int d = tid + i * 256;
        float v = (lv[i] - mu) * inv * w[d];
        size_t idx = (size_t)t * D_ + d;
        outf[idx] = v;
        outh[idx] = __float2half_rn(v);
        xs[d] = v;
    }
    __syncthreads();
    // router: warp e computes logit e
    int we = tid >> 5, lane = tid & 31;
    const float* rw = RW + (size_t)we * D_;
    float dot = 0.f;
    for (int d = lane; d < D_; d += 32) dot += xs[d] * rw[d];
#pragma unroll
    for (int o = 16; o; o >>= 1) dot += __shfl_xor_sync(0xffffffffu, dot, o);
    if (lane == 0) lg[we] = dot;
    __syncthreads();
    if (tid == 0) {
        float mx = -1e30f;
#pragma unroll
        for (int e = 0; e < E_; ++e) mx = fmaxf(mx, lg[e]);
        float p[E_], sum = 0.f;
#pragma unroll
        for (int e = 0; e < E_; ++e) { p[e] = expf(lg[e] - mx); sum += p[e]; }
        float invs = 1.0f / sum;
#pragma unroll
        for (int e = 0; e < E_; ++e) {
            float pe = p[e] * invs;
            p[e] = fminf(fmaxf(pe + 1e-9f, 1e-9f), 1.0f - 1e-9f);
        }
        int e0 = 0;
#pragma unroll
        for (int e = 1; e < E_; ++e) if (p[e] > p[e0]) e0 = e;
        int e1 = -1;
#pragma unroll
        for (int e = 0; e < E_; ++e) {
            if (e == e0) continue;
            if (e1 < 0 || p[e] > p[e1]) e1 = e;
        }
        float invp = 1.0f / (p[e0] + p[e1]);
        int pos0 = atomicAdd(&cnt[e0], 1);
        assign[e0 * BT_ + pos0] = 2 * t;
        int pos1 = atomicAdd(&cnt[e1], 1);
        assign[e1 * BT_ + pos1] = 2 * t + 1;
        wt[2 * t]     = p[e0] * invp;
        wt[2 * t + 1] = p[e1] * invp;
    }
}

__global__ void __launch_bounds__(256) combine_kernel(
    const float* __restrict__ Con, float* __restrict__ out)
{
    int i = blockIdx.x * 256 + threadIdx.x;
    int t = i >> 10;
    int d = i & 1023;
    out[i] += Con[(size_t)(2 * t) * D_ + d] + Con[(size_t)(2 * t + 1) * D_ + d];
}

extern "C" void kernel_launch(void* const* d_in, const int* in_sizes, int n_in,
                              void* d_out, int out_size)
{
    const float* x        = (const float*)d_in[0];
    const float* c        = (const float*)d_in[1];
    const float* ln1_w    = (const float*)d_in[2];
    const float* w_qkv    = (const float*)d_in[3];
    const float* w_proj   = (const float*)d_in[4];
    const float* ln2_w    = (const float*)d_in[5];
    const float* router_w = (const float*)d_in[6];
    const float* ew1      = (const float*)d_in[7];
    const float* ew2      = (const float*)d_in[8];
    float* out = (float*)d_out;

    __half *ph16h, *ph16l, *pqkvh, *pqkvl, *poh, *pol, *px2h;
    __half *pwqkvh, *pwqkvl, *pwprojh, *pwprojl, *phid;
    float *px1, *pcon, *pwt;
    int *pcnt, *pasn;
    cudaGetSymbolAddress((void**)&ph16h,   g_h16h);
    cudaGetSymbolAddress((void**)&ph16l,   g_h16l);
    cudaGetSymbolAddress((void**)&pqkvh,   g_qkvh);
    cudaGetSymbolAddress((void**)&pqkvl,   g_qkvl);
    cudaGetSymbolAddress((void**)&poh,     g_oh);
    cudaGetSymbolAddress((void**)&pol,     g_ol);
    cudaGetSymbolAddress((void**)&px1,     g_x1);
    cudaGetSymbolAddress((void**)&px2h,    g_x2h);
    cudaGetSymbolAddress((void**)&pwqkvh,  g_wqkvh);
    cudaGetSymbolAddress((void**)&pwqkvl,  g_wqkvl);
    cudaGetSymbolAddress((void**)&pwprojh, g_wprojh);
    cudaGetSymbolAddress((void**)&pwprojl, g_wprojl);
    cudaGetSymbolAddress((void**)&phid,    g_hid);
    cudaGetSymbolAddress((void**)&pcon,    g_contrib);
    cudaGetSymbolAddress((void**)&pwt,     g_wt);
    cudaGetSymbolAddress((void**)&pcnt,    g_count);
    cudaGetSymbolAddress((void**)&pasn,    g_assign);

    const int SM_SPLIT = 2 * 4 * 10240;   // 81920
    const int SM_1P    = 2 * 2 * 10240;   // 40960
    const int SM_ATTN  = 73728;
    cudaFuncSetAttribute((void*)tgemm<0,0,true,false>,  cudaFuncAttributeMaxDynamicSharedMemorySize, SM_SPLIT);
    cudaFuncSetAttribute((void*)tgemm<0,1,true,false>,  cudaFuncAttributeMaxDynamicSharedMemorySize, SM_SPLIT);
    cudaFuncSetAttribute((void*)tgemm<1,2,false,true>,  cudaFuncAttributeMaxDynamicSharedMemorySize, SM_1P);
    cudaFuncSetAttribute((void*)tgemm<2,3,false,true>,  cudaFuncAttributeMaxDynamicSharedMemorySize, SM_1P);
    cudaFuncSetAttribute((void*)attn_hmma,              cudaFuncAttributeMaxDynamicSharedMemorySize, SM_ATTN);

    zero_counts_kernel<<<1, 32>>>(pcnt);
    convk<<<(3 * D_ * D_) / 1024, 256>>>(w_qkv, pwqkvh, pwqkvl);
    convk<<<(D_ * D_) / 1024, 256>>>(w_proj, pwprojh, pwprojl);
    ln1_kernel<<<BT_, 256>>>(x, ln1_w, c, ph16h, ph16l);
    // qkv (split) -> fp16 hi/lo
    tgemm<0,0,true,false><<<dim3(3 * D_ / 128, BT_ / 128), 256, SM_SPLIT>>>(
        ph16h, ph16l, pwqkvh, pwqkvl, nullptr, pqkvh, pqkvl, nullptr,
        nullptr, nullptr, nullptr, BT_, D_, D_, D_, 3 * D_, 0);
    attn_hmma<<<dim3(T_ / 128, B_ * H_), 256, SM_ATTN>>>(pqkvh, pqkvl, poh, pol);
    // x1 = x + o @ w_proj^T (split)
    tgemm<0,1,true,false><<<dim3(D_ / 128, BT_ / 128), 256, SM_SPLIT>>>(
        poh, pol, pwprojh, pwprojl, nullptr, px1, nullptr, x,
        nullptr, nullptr, nullptr, BT_, D_, D_, D_, D_, 0);
    // fused ln2 + router
    ln2_router_kernel<<<BT_, 256>>>(px1, ln2_w, out, px2h, router_w, pcnt, pasn, pwt);
    // moe1: hid = gelu(x2 @ w1^T), B read as fp32 + converted in-kernel
    tgemm<1,2,false,true><<<dim3(FF_ / 128, BT_ / 128, E_), 256, SM_1P>>>(
        px2h, nullptr, nullptr, nullptr, ew1, phid, nullptr, nullptr,
        pcnt, pasn, nullptr, 0, D_, D_, D_, FF_, (size_t)FF_ * D_);
    // moe2: contrib = wt * (hid @ w2^T), B fp32 in-kernel
    tgemm<2,3,false,true><<<dim3(D_ / 128, BT_ / 128, E_), 256, SM_1P>>>(
        phid, nullptr, nullptr, nullptr, ew2, pcon, nullptr, nullptr,
        pcnt, pasn, pwt, 0, FF_, FF_, FF_, D_, (size_t)D_ * FF_);
    combine_kernel<<<(BT_ * D_) / 256, 256>>>(pcon, out);
}

// round 15
// speedup vs baseline: 1.2066x; 1.2066x over previous
#include <cuda_runtime.h>
#include <cuda_fp16.h>
#include <math.h>
#include <stdint.h>

#define B_ 4
#define T_ 1024
#define D_ 1024
#define H_ 16
#define DH_ 64
#define E_ 8
#define FF_ 4096
#define BT_ (B_*T_)
#define NASSIGN (BT_*2)

// ---------------- scratch ----------------
__device__ __half g_h16h[BT_ * D_];
__device__ __half g_h16l[BT_ * D_];
__device__ __half g_qkvh[BT_ * 3 * D_];
__device__ __half g_qkvl[BT_ * 3 * D_];
__device__ __half g_oh[BT_ * D_];
__device__ __half g_ol[BT_ * D_];
__device__ float  g_x1[BT_ * D_];
__device__ __half g_x2h[BT_ * D_];
__device__ __half g_wqkvh[3 * D_ * D_];
__device__ __half g_wqkvl[3 * D_ * D_];
__device__ __half g_wprojh[D_ * D_];
__device__ __half g_wprojl[D_ * D_];
__device__ __half g_w1h[(size_t)E_ * FF_ * D_];
__device__ __half g_w2h[(size_t)E_ * D_ * FF_];
__device__ __half g_hid[(size_t)NASSIGN * FF_];
__device__ int    g_count[E_];
__device__ int    g_assign[E_ * BT_];
__device__ float  g_wt[NASSIGN];

__device__ __forceinline__ float gelu_exact(float x) {
    return 0.5f * x * (1.0f + erff(x * 0.70710678118654752440f));
}
__device__ __forceinline__ uint32_t smem_u32(const void* p) {
    uint32_t a;
    asm("{ .reg .u64 t; cvta.to.shared.u64 t, %1; cvt.u32.u64 %0, t; }" : "=r"(a) : "l"(p));
    return a;
}
__device__ __forceinline__ void ldmx4(uint32_t* r, uint32_t addr) {
    asm volatile("ldmatrix.sync.aligned.m8n8.x4.shared.b16 {%0,%1,%2,%3}, [%4];"
        : "=r"(r[0]), "=r"(r[1]), "=r"(r[2]), "=r"(r[3]) : "r"(addr));
}
__device__ __forceinline__ void ldmx4t(uint32_t* r, uint32_t addr) {
    asm volatile("ldmatrix.sync.aligned.m8n8.x4.trans.shared.b16 {%0,%1,%2,%3}, [%4];"
        : "=r"(r[0]), "=r"(r[1]), "=r"(r[2]), "=r"(r[3]) : "r"(addr));
}
__device__ __forceinline__ void mma16816(float* c, const uint32_t* a, uint32_t b0, uint32_t b1) {
    asm volatile(
        "mma.sync.aligned.m16n8k16.row.col.f32.f16.f16.f32 "
        "{%0,%1,%2,%3}, {%4,%5,%6,%7}, {%8,%9}, {%0,%1,%2,%3};"
        : "+f"(c[0]), "+f"(c[1]), "+f"(c[2]), "+f"(c[3])
        : "r"(a[0]), "r"(a[1]), "r"(a[2]), "r"(a[3]), "r"(b0), "r"(b1));
}
__device__ __forceinline__ void packsplit(uint32_t& h, uint32_t& l, float x, float y) {
    __half hx = __float2half_rn(x), hy = __float2half_rn(y);
    __half lx = __float2half_rn(x - __half2float(hx));
    __half ly = __float2half_rn(y - __half2float(hy));
    __half2 hh; hh.x = hx; hh.y = hy; h = *(uint32_t*)&hh;
    __half2 ll; ll.x = lx; ll.y = ly; l = *(uint32_t*)&ll;
}

// ---------------- weight convert ----------------
template<bool SPLIT>
__global__ void __launch_bounds__(256) convk(
    const float* __restrict__ in, __half* __restrict__ oh, __half* __restrict__ ol)
{
    size_t i = ((size_t)blockIdx.x * 256 + threadIdx.x) * 4;
    float4 v = *(const float4*)(in + i);
    __half2 h0 = __floats2half2_rn(v.x, v.y);
    __half2 h1 = __floats2half2_rn(v.z, v.w);
    *(__half2*)(oh + i) = h0; *(__half2*)(oh + i + 2) = h1;
    if (SPLIT) {
        float2 f0 = __half22float2(h0), f1 = __half22float2(h1);
        *(__half2*)(ol + i) = __floats2half2_rn(v.x - f0.x, v.y - f0.y);
        *(__half2*)(ol + i + 2) = __floats2half2_rn(v.z - f1.x, v.w - f1.y);
    }
}

// =====================================================================
// HMMA GEMM, pre-converted fp16 inputs. 128x128 tile, BK=32, 8 warps.
// GM: 0=dense, 1=gather token(slot>>1), 2=gather slot.
// EM: 0=qkv hi/lo fp16, 1=f32 + residual, 2=gelu->fp16, 3=*wt atomicAdd f32.
// =====================================================================
template<int GM, int EM, bool SPLIT>
__global__ void __launch_bounds__(256, 1) tgemm(
    const __half* __restrict__ Ah, const __half* __restrict__ Al,
    const __half* __restrict__ Bh, const __half* __restrict__ Bl,
    void* __restrict__ Cv, __half* __restrict__ Cv2, const float* __restrict__ Rv,
    const int* __restrict__ cnt, const int* __restrict__ assign,
    const float* __restrict__ wt,
    int Mdense, int K, int lda, int ldb, int ldc, size_t strideB)
{
    extern __shared__ char smem[];
    __shared__ int slist[128];
    constexpr int TILE = 10240;
    constexpr int NT = SPLIT ? 4 : 2;
    constexpr int STAGE = NT * TILE;

    int tid = threadIdx.x, lane = tid & 31, warp = tid >> 5;
    int m0 = blockIdx.y * 128, n0 = blockIdx.x * 128;

    int Mlim = Mdense;
    if (GM != 0) {
        int e = blockIdx.z;
        Mlim = cnt[e];
        if (m0 >= Mlim) return;
        const int* lst = assign + e * BT_;
        Bh = Bh + (size_t)e * strideB;
        if (tid < 128) {
            int idx = m0 + tid;
            if (idx > Mlim - 1) idx = Mlim - 1;
            slist[tid] = lst[idx];
        }
        __syncthreads();
    }
    uint32_t sb = smem_u32(smem);

    int ca = tid & 3;
    size_t aoffg[2], boffg[2];
#pragma unroll
    for (int i = 0; i < 2; ++i) {
        int r = (tid >> 2) + i * 64;
        int src;
        if (GM == 0)      src = m0 + r;
        else if (GM == 1) src = slist[r] >> 1;
        else              src = slist[r];
        aoffg[i] = (size_t)src * lda + ca * 8;
        boffg[i] = (size_t)(n0 + r) * ldb + ca * 8;
    }

    uint4 arH[2], arL[2], brH[2], brL[2];
    auto ldg = [&](int kc) {
        int k0 = kc * 32;
#pragma unroll
        for (int i = 0; i < 2; ++i) {
            arH[i] = *(const uint4*)(Ah + aoffg[i] + k0);
            brH[i] = *(const uint4*)(Bh + boffg[i] + k0);
            if (SPLIT) {
                arL[i] = *(const uint4*)(Al + aoffg[i] + k0);
                brL[i] = *(const uint4*)(Bl + boffg[i] + k0);
            }
        }
    };
    auto sts = [&](int stg) {
        char* base = smem + stg * STAGE;
#pragma unroll
        for (int i = 0; i < 2; ++i) {
            int r = (tid >> 2) + i * 64;
            int off = r * 80 + ca * 16;
            *(uint4*)(base + off) = arH[i];
            *(uint4*)(base + (SPLIT ? 2 : 1) * TILE + off) = brH[i];
            if (SPLIT) {
                *(uint4*)(base + TILE + off) = arL[i];
                *(uint4*)(base + 3 * TILE + off) = brL[i];
            }
        }
    };

    float acc[4][4][4];
#pragma unroll
    for (int i = 0; i < 4; ++i)
#pragma unroll
        for (int j = 0; j < 4; ++j)
#pragma unroll
            for (int k = 0; k < 4; ++k) acc[i][j][k] = 0.f;

    int wm = (warp >> 2) * 64, wn = (warp & 3) * 32;
    uint32_t frag_off = (uint32_t)((lane & 15) * 80 + (lane >> 4) * 16);

    auto compute = [&](int stg) {
        uint32_t base = sb + stg * STAGE;
        uint32_t AhS = base;
        uint32_t AlS = base + TILE;
        uint32_t BhS = base + (SPLIT ? 2 : 1) * TILE;
        uint32_t BlS = BhS + TILE;
#pragma unroll
        for (int ks = 0; ks < 2; ++ks) {
            uint32_t ko = ks * 32;
            uint32_t ah[4][4], bh[2][4];
#pragma unroll
            for (int mf = 0; mf < 4; ++mf)
                ldmx4(ah[mf], AhS + (wm + mf * 16) * 80 + frag_off + ko);
#pragma unroll
            for (int np = 0; np < 2; ++np)
                ldmx4(bh[np], BhS + (wn + np * 16) * 80 + frag_off + ko);
            if (!SPLIT) {
#pragma unroll
                for (int mf = 0; mf < 4; ++mf)
#pragma unroll
                    for (int nf = 0; nf < 4; ++nf) {
                        int np = nf >> 1, u = nf & 1;
                        mma16816(acc[mf][nf], ah[mf], bh[np][u], bh[np][u + 2]);
                    }
            } else {
                uint32_t al[4][4], bl[2][4];
#pragma unroll
                for (int mf = 0; mf < 4; ++mf)
                    ldmx4(al[mf], AlS + (wm + mf * 16) * 80 + frag_off + ko);
#pragma unroll
                for (int np = 0; np < 2; ++np)
                    ldmx4(bl[np], BlS + (wn + np * 16) * 80 + frag_off + ko);
#pragma unroll
                for (int mf = 0; mf < 4; ++mf)
#pragma unroll
                    for (int nf = 0; nf < 4; ++nf) {
                        int np = nf >> 1, u = nf & 1;
                        mma16816(acc[mf][nf], ah[mf], bh[np][u], bh[np][u + 2]);
                        mma16816(acc[mf][nf], ah[mf], bl[np][u], bl[np][u + 2]);
                        mma16816(acc[mf][nf], al[mf], bh[np][u], bh[np][u + 2]);
                    }
            }
        }
    };

    const int NC = K / 32;
    ldg(0); sts(0); __syncthreads();
    for (int c = 0; c < NC; ++c) {
        if (c + 1 < NC) ldg(c + 1);
        compute(c & 1);
        if (c + 1 < NC) sts((c + 1) & 1);
        __syncthreads();
    }

#pragma unroll
    for (int mf = 0; mf < 4; ++mf) {
#pragma unroll
        for (int nf = 0; nf < 4; ++nf) {
            int r0 = wm + mf * 16 + (lane >> 2);
            int gc = n0 + wn + nf * 8 + (lane & 3) * 2;
            float* cc = acc[mf][nf];
#pragma unroll
            for (int hf = 0; hf < 2; ++hf) {
                int rl = r0 + hf * 8;
                float v0 = cc[hf * 2], v1 = cc[hf * 2 + 1];
                if (GM == 0 || (m0 + rl) < Mlim) {
                    if (EM == 0) {
                        uint32_t hh, ll;
                        packsplit(hh, ll, v0, v1);
                        size_t idx = (size_t)(m0 + rl) * ldc + gc;
                        *(uint32_t*)((__half*)Cv + idx) = hh;
                        *(uint32_t*)(Cv2 + idx) = ll;
                    } else if (EM == 1) {
                        const float* R = Rv + (size_t)(m0 + rl) * ldc + gc;
                        float2 st; st.x = v0 + R[0]; st.y = v1 + R[1];
                        *(float2*)((float*)Cv + (size_t)(m0 + rl) * ldc + gc) = st;
                    } else if (EM == 2) {
                        int a = slist[rl];
                        __half2 hh = __floats2half2_rn(gelu_exact(v0), gelu_exact(v1));
                        *(__half2*)((__half*)Cv + (size_t)a * ldc + gc) = hh;
                    } else {
                        int a = slist[rl];
                        float wv = wt[a];
                        float* O = (float*)Cv + (size_t)(a >> 1) * ldc + gc;
                        atomicAdd(O + 0, wv * v0);
                        atomicAdd(O + 1, wv * v1);
                    }
                }
            }
        }
    }
}

// =====================================================================
// HMMA flash attention (R7): fp16 hi/lo split QK and PV. 128 q-rows/block,
// 8 warps x 16 rows, 64-key tiles, causal, row stride 144 B.
// =====================================================================
__global__ void __launch_bounds__(256, 1) attn_hmma(
    const __half* __restrict__ qh, const __half* __restrict__ ql,
    __half* __restrict__ Oh, __half* __restrict__ Ol)
{
    extern __shared__ char sm[];
    const int QH = 0, QL = 18432, KH = 36864, KL = 46080, VH = 55296, VL = 64512;
    int bh = blockIdx.y;
    int b = bh >> 4, h = bh & 15;
    int q0 = blockIdx.x * 128;
    int tid = threadIdx.x, lane = tid & 31, warp = tid >> 5;
    uint32_t sb = smem_u32(sm);
    size_t base3d = (size_t)(b * T_) * 3 * D_ + h * 64;

#pragma unroll
    for (int i = 0; i < 4; ++i) {
        int q = tid + i * 256; int r = q >> 3, c = q & 7;
        size_t g = base3d + (size_t)(q0 + r) * 3 * D_ + c * 8;
        *(uint4*)(sm + QH + r * 144 + c * 16) = *(const uint4*)(qh + g);
        *(uint4*)(sm + QL + r * 144 + c * 16) = *(const uint4*)(ql + g);
    }

    float Oacc[8][4];
#pragma unroll
    for (int i = 0; i < 8; ++i)
#pragma unroll
        for (int j = 0; j < 4; ++j) Oacc[i][j] = 0.f;
    float m_i[2] = { -1e30f, -1e30f }, l_i[2] = { 0.f, 0.f };

    int wm = warp * 16;
    uint32_t frag_off = (uint32_t)((lane & 15) * 144 + (lane >> 4) * 16);
    int nkt = q0 / 64 + 2;
    __syncthreads();

    for (int kt = 0; kt < nkt; ++kt) {
        int k0 = kt * 64;
#pragma unroll
        for (int i = 0; i < 2; ++i) {
            int q = tid + i * 256; int r = q >> 3, c = q & 7;
            size_t g = base3d + (size_t)(k0 + r) * 3 * D_ + c * 8;
            int off = r * 144 + c * 16;
            *(uint4*)(sm + KH + off) = *(const uint4*)(qh + g + D_);
            *(uint4*)(sm + KL + off) = *(const uint4*)(ql + g + D_);
            *(uint4*)(sm + VH + off) = *(const uint4*)(qh + g + 2 * D_);
            *(uint4*)(sm + VL + off) = *(const uint4*)(ql + g + 2 * D_);
        }
        __syncthreads();

        if (k0 <= q0 + wm + 15) {
            float S[8][4];
#pragma unroll
            for (int i = 0; i < 8; ++i)
#pragma unroll
                for (int j = 0; j < 4; ++j) S[i][j] = 0.f;
#pragma unroll
            for (int kc = 0; kc < 4; ++kc) {
                uint32_t ko = kc * 32;
                uint32_t aH[4], aL[4];
                ldmx4(aH, sb + QH + wm * 144 + frag_off + ko);
                ldmx4(aL, sb + QL + wm * 144 + frag_off + ko);
#pragma unroll
                for (int np = 0; np < 4; ++np) {
                    uint32_t bH[4], bL[4];
                    ldmx4(bH, sb + KH + np * 16 * 144 + frag_off + ko);
                    ldmx4(bL, sb + KL + np * 16 * 144 + frag_off + ko);
#pragma unroll
                    for (int u = 0; u < 2; ++u) {
                        int nf = np * 2 + u;
                        mma16816(S[nf], aH, bH[u], bH[u + 2]);
                        mma16816(S[nf], aH, bL[u], bL[u + 2]);
                        mma16816(S[nf], aL, bH[u], bH[u + 2]);
                    }
                }
            }
            int qg0 = q0 + wm + (lane >> 2);
            int qg1 = qg0 + 8;
            bool dm = (k0 + 63) > (q0 + wm);
            float mx0 = -1e30f, mx1 = -1e30f;
#pragma unroll
            for (int nf = 0; nf < 8; ++nf) {
                int kg = k0 + nf * 8 + (lane & 3) * 2;
                float* s = S[nf];
                s[0] *= 0.125f; s[1] *= 0.125f; s[2] *= 0.125f; s[3] *= 0.125f;
                if (dm) {
                    if (kg > qg0)     s[0] = -1e30f;
                    if (kg + 1 > qg0) s[1] = -1e30f;
                    if (kg > qg1)     s[2] = -1e30f;
                    if (kg + 1 > qg1) s[3] = -1e30f;
                }
                mx0 = fmaxf(mx0, fmaxf(s[0], s[1]));
                mx1 = fmaxf(mx1, fmaxf(s[2], s[3]));
            }
            mx0 = fmaxf(mx0, __shfl_xor_sync(0xffffffffu, mx0, 1));
            mx0 = fmaxf(mx0, __shfl_xor_sync(0xffffffffu, mx0, 2));
            mx1 = fmaxf(mx1, __shfl_xor_sync(0xffffffffu, mx1, 1));
            mx1 = fmaxf(mx1, __shfl_xor_sync(0xffffffffu, mx1, 2));
            float mn0 = fmaxf(m_i[0], mx0), mn1 = fmaxf(m_i[1], mx1);
            float a0 = expf(m_i[0] - mn0), a1 = expf(m_i[1] - mn1);
            float rs0 = 0.f, rs1 = 0.f;
#pragma unroll
            for (int nf = 0; nf < 8; ++nf) {
                float* s = S[nf];
                s[0] = expf(s[0] - mn0); s[1] = expf(s[1] - mn0);
                s[2] = expf(s[2] - mn1); s[3] = expf(s[3] - mn1);
                rs0 += s[0] + s[1]; rs1 += s[2] + s[3];
            }
            rs0 += __shfl_xor_sync(0xffffffffu, rs0, 1);
            rs0 += __shfl_xor_sync(0xffffffffu, rs0, 2);
            rs1 += __shfl_xor_sync(0xffffffffu, rs1, 1);
            rs1 += __shfl_xor_sync(0xffffffffu, rs1, 2);
            l_i[0] = l_i[0] * a0 + rs0;
            l_i[1] = l_i[1] * a1 + rs1;
            m_i[0] = mn0; m_i[1] = mn1;
#pragma unroll
            for (int nf = 0; nf < 8; ++nf) {
                Oacc[nf][0] *= a0; Oacc[nf][1] *= a0;
                Oacc[nf][2] *= a1; Oacc[nf][3] *= a1;
            }
#pragma unroll
            for (int kc = 0; kc < 4; ++kc) {
                uint32_t pH[4], pL[4];
                float* sA = S[2 * kc]; float* sB = S[2 * kc + 1];
                packsplit(pH[0], pL[0], sA[0], sA[1]);
                packsplit(pH[1], pL[1], sA[2], sA[3]);
                packsplit(pH[2], pL[2], sB[0], sB[1]);
                packsplit(pH[3], pL[3], sB[2], sB[3]);
                uint32_t vaddr = (uint32_t)((kc * 16 + (lane & 7) + ((lane >> 4) & 1) * 8) * 144
                                            + ((lane >> 3) & 1) * 16);
#pragma unroll
                for (int g = 0; g < 4; ++g) {
                    uint32_t vH[4], vL[4];
                    ldmx4t(vH, sb + VH + vaddr + g * 32);
                    ldmx4t(vL, sb + VL + vaddr + g * 32);
                    mma16816(Oacc[g * 2], pH, vH[0], vH[2]);
                    mma16816(Oacc[g * 2], pH, vL[0], vL[2]);
                    mma16816(Oacc[g * 2], pL, vH[0], vH[2]);
                    mma16816(Oacc[g * 2 + 1], pH, vH[1], vH[3]);
                    mma16816(Oacc[g * 2 + 1], pH, vL[1], vL[3]);
                    mma16816(Oacc[g * 2 + 1], pL, vH[1], vH[3]);
                }
            }
        }
        __syncthreads();
    }

    float inv0 = 1.0f / l_i[0], inv1 = 1.0f / l_i[1];
    int r0g = b * T_ + q0 + wm + (lane >> 2);
#pragma unroll
    for (int nf = 0; nf < 8; ++nf) {
        int col = h * 64 + nf * 8 + (lane & 3) * 2;
        uint32_t hh, ll;
        packsplit(hh, ll, Oacc[nf][0] * inv0, Oacc[nf][1] * inv0);
        size_t i0 = (size_t)r0g * D_ + col;
        *(uint32_t*)(Oh + i0) = hh;
        *(uint32_t*)(Ol + i0) = ll;
        packsplit(hh, ll, Oacc[nf][2] * inv1, Oacc[nf][3] * inv1);
        size_t i1 = (size_t)(r0g + 8) * D_ + col;
        *(uint32_t*)(Oh + i1) = hh;
        *(uint32_t*)(Ol + i1) = ll;
    }
}

__global__ void zero_counts_kernel(int* cnt) {
    if (threadIdx.x < E_) cnt[threadIdx.x] = 0;
}

// ln1 -> fp16 hi/lo (with cond)
__global__ void __launch_bounds__(256) ln1_kernel(
    const float* __restrict__ x, const float* __restrict__ w,
    const float* __restrict__ c, __half* __restrict__ outh, __half* __restrict__ outl)
{
    int t = blockIdx.x;
    int b = t / T_;
    int tid = threadIdx.x;
    const float* xr = x + (size_t)t * D_;
    float lv[4];
    float s = 0.f, ss = 0.f;
#pragma unroll
    for (int i = 0; i < 4; ++i) {
        lv[i] = xr[tid + i * 256];
        s += lv[i]; ss += lv[i] * lv[i];
    }
    __shared__ float red0[8], red1[8];
#pragma unroll
    for (int o = 16; o; o >>= 1) {
        s  += __shfl_xor_sync(0xffffffffu, s, o);
        ss += __shfl_xor_sync(0xffffffffu, ss, o);
    }
    if ((tid & 31) == 0) { red0[tid >> 5] = s; red1[tid >> 5] = ss; }
    __syncthreads();
    if (tid < 32) {
        s  = (tid < 8) ? red0[tid] : 0.f;
        ss = (tid < 8) ? red1[tid] : 0.f;
#pragma unroll
        for (int o = 4; o; o >>= 1) {
            s  += __shfl_xor_sync(0xffffffffu, s, o);
            ss += __shfl_xor_sync(0xffffffffu, ss, o);
        }
        if (tid == 0) { red0[0] = s; red1[0] = ss; }
    }
    __syncthreads();
    float mu  = red0[0] * (1.0f / D_);
    float var = red1[0] * (1.0f / D_) - mu * mu;
    float inv = rsqrtf(var + 1e-5f);
#pragma unroll
    for (int i = 0; i < 4; ++i) {
        int d = tid + i * 256;
        float v = (lv[i] - mu) * inv * w[d] + c[(size_t)b * D_ + d];
        size_t idx = (size_t)t * D_ + d;
        __half hh = __float2half_rn(v);
        outh[idx] = hh;
        outl[idx] = __float2half_rn(v - __half2float(hh));
    }
}

// fused ln2 + router
__global__ void __launch_bounds__(256) ln2_router_kernel(
    const float* __restrict__ x, const float* __restrict__ w,
    float* __restrict__ outf, __half* __restrict__ outh,
    const float* __restrict__ RW,
    int* __restrict__ cnt, int* __restrict__ assign, float* __restrict__ wt)
{
    int t = blockIdx.x;
    int tid = threadIdx.x;
    const float* xr = x + (size_t)t * D_;
    __shared__ float xs[D_];
    __shared__ float red0[8], red1[8], lg[E_];
    float lv[4];
    float s = 0.f, ss = 0.f;
#pragma unroll
    for (int i = 0; i < 4; ++i) {
        lv[i] = xr[tid + i * 256];
        s += lv[i]; ss += lv[i] * lv[i];
    }
#pragma unroll
    for (int o = 16; o; o >>= 1) {
        s  += __shfl_xor_sync(0xffffffffu, s, o);
        ss += __shfl_xor_sync(0xffffffffu, ss, o);
    }
    if ((tid & 31) == 0) { red0[tid >> 5] = s; red1[tid >> 5] = ss; }
    __syncthreads();
    if (tid < 32) {
        s  = (tid < 8) ? red0[tid] : 0.f;
        ss = (tid < 8) ? red1[tid] : 0.f;
#pragma unroll
        for (int o = 4; o; o >>= 1) {
            s  += __shfl_xor_sync(0xffffffffu, s, o);
            ss += __shfl_xor_sync(0xffffffffu, ss, o);
        }
        if (tid == 0) { red0[0] = s; red1[0] = ss; }
    }
    __syncthreads();
    float mu  = red0[0] * (1.0f / D_);
    float var = red1[0] * (1.0f / D_) - mu * mu;
    float inv = rsqrtf(var + 1e-5f);
#pragma unroll
    for (int i = 0; i < 4; ++i) {
        int d = tid + i * 256;
        float v = (lv[i] - mu) * inv * w[d];
        size_t idx = (size_t)t * D_ + d;
        outf[idx] = v;
        outh[idx] = __float2half_rn(v);
        xs[d] = v;
    }
    __syncthreads();
    int we = tid >> 5, lane = tid & 31;
    const float* rw = RW + (size_t)we * D_;
    float dot = 0.f;
    for (int d = lane; d < D_; d += 32) dot += xs[d] * rw[d];
#pragma unroll
    for (int o = 16; o; o >>= 1) dot += __shfl_xor_sync(0xffffffffu, dot, o);
    if (lane == 0) lg[we] = dot;
    __syncthreads();
    if (tid == 0) {
        float mx = -1e30f;
#pragma unroll
        for (int e = 0; e < E_; ++e) mx = fmaxf(mx, lg[e]);
        float p[E_], sum = 0.f;
#pragma unroll
        for (int e = 0; e < E_; ++e) { p[e] = expf(lg[e] - mx); sum += p[e]; }
        float invs = 1.0f / sum;
#pragma unroll
        for (int e = 0; e < E_; ++e) {
            float pe = p[e] * invs;
            p[e] = fminf(fmaxf(pe + 1e-9f, 1e-9f), 1.0f - 1e-9f);
        }
        int e0 = 0;
#pragma unroll
        for (int e = 1; e < E_; ++e) if (p[e] > p[e0]) e0 = e;
        int e1 = -1;
#pragma unroll
        for (int e = 0; e < E_; ++e) {
            if (e == e0) continue;
            if (e1 < 0 || p[e] > p[e1]) e1 = e;
        }
        float invp = 1.0f / (p[e0] + p[e1]);
        int pos0 = atomicAdd(&cnt[e0], 1);
        assign[e0 * BT_ + pos0] = 2 * t;
        int pos1 = atomicAdd(&cnt[e1], 1);
        assign[e1 * BT_ + pos1] = 2 * t + 1;
        wt[2 * t]     = p[e0] * invp;
        wt[2 * t + 1] = p[e1] * invp;
    }
}

extern "C" void kernel_launch(void* const* d_in, const int* in_sizes, int n_in,
                              void* d_out, int out_size)
{
    const float* x        = (const float*)d_in[0];
    const float* c        = (const float*)d_in[1];
    const float* ln1_w    = (const float*)d_in[2];
    const float* w_qkv    = (const float*)d_in[3];
    const float* w_proj   = (const float*)d_in[4];
    const float* ln2_w    = (const float*)d_in[5];
    const float* router_w = (const float*)d_in[6];
    const float* ew1      = (const float*)d_in[7];
    const float* ew2      = (const float*)d_in[8];
    float* out = (float*)d_out;

    __half *ph16h, *ph16l, *pqkvh, *pqkvl, *poh, *pol, *px2h;
    __half *pwqkvh, *pwqkvl, *pwprojh, *pwprojl, *pw1h, *pw2h, *phid;
    float *px1, *pwt;
    int *pcnt, *pasn;
    cudaGetSymbolAddress((void**)&ph16h,   g_h16h);
    cudaGetSymbolAddress((void**)&ph16l,   g_h16l);
    cudaGetSymbolAddress((void**)&pqkvh,   g_qkvh);
    cudaGetSymbolAddress((void**)&pqkvl,   g_qkvl);
    cudaGetSymbolAddress((void**)&poh,     g_oh);
    cudaGetSymbolAddress((void**)&pol,     g_ol);
    cudaGetSymbolAddress((void**)&px1,     g_x1);
    cudaGetSymbolAddress((void**)&px2h,    g_x2h);
    cudaGetSymbolAddress((void**)&pwqkvh,  g_wqkvh);
    cudaGetSymbolAddress((void**)&pwqkvl,  g_wqkvl);
    cudaGetSymbolAddress((void**)&pwprojh, g_wprojh);
    cudaGetSymbolAddress((void**)&pwprojl, g_wprojl);
    cudaGetSymbolAddress((void**)&pw1h,    g_w1h);
    cudaGetSymbolAddress((void**)&pw2h,    g_w2h);
    cudaGetSymbolAddress((void**)&phid,    g_hid);
    cudaGetSymbolAddress((void**)&pwt,     g_wt);
    cudaGetSymbolAddress((void**)&pcnt,    g_count);
    cudaGetSymbolAddress((void**)&pasn,    g_assign);

    const int SM_SPLIT = 2 * 4 * 10240;   // 81920
    const int SM_1P    = 2 * 2 * 10240;   // 40960
    const int SM_ATTN  = 73728;
    cudaFuncSetAttribute(tgemm<0,0,true>,  cudaFuncAttributeMaxDynamicSharedMemorySize, SM_SPLIT);
    cudaFuncSetAttribute(tgemm<0,1,true>,  cudaFuncAttributeMaxDynamicSharedMemorySize, SM_SPLIT);
    cudaFuncSetAttribute(tgemm<1,2,false>, cudaFuncAttributeMaxDynamicSharedMemorySize, SM_1P);
    cudaFuncSetAttribute(tgemm<2,3,false>, cudaFuncAttributeMaxDynamicSharedMemorySize, SM_1P);
    cudaFuncSetAttribute(attn_hmma,        cudaFuncAttributeMaxDynamicSharedMemorySize, SM_ATTN);

    zero_counts_kernel<<<1, 32>>>(pcnt);
    convk<true><<<(3 * D_ * D_) / 1024, 256>>>(w_qkv, pwqkvh, pwqkvl);
    convk<true><<<(D_ * D_) / 1024, 256>>>(w_proj, pwprojh, pwprojl);
    convk<false><<<(int)(((size_t)E_ * FF_ * D_) / 1024), 256>>>(ew1, pw1h, nullptr);
    convk<false><<<(int)(((size_t)E_ * D_ * FF_) / 1024), 256>>>(ew2, pw2h, nullptr);
    ln1_kernel<<<BT_, 256>>>(x, ln1_w, c, ph16h, ph16l);
    // qkv (split) -> fp16 hi/lo
    tgemm<0,0,true><<<dim3(3 * D_ / 128, BT_ / 128), 256, SM_SPLIT>>>(
        ph16h, ph16l, pwqkvh, pwqkvl, pqkvh, pqkvl, nullptr,
        nullptr, nullptr, nullptr, BT_, D_, D_, D_, 3 * D_, 0);
    attn_hmma<<<dim3(T_ / 128, B_ * H_), 256, SM_ATTN>>>(pqkvh, pqkvl, poh, pol);
    // x1 = x + o @ w_proj^T (split)
    tgemm<0,1,true><<<dim3(D_ / 128, BT_ / 128), 256, SM_SPLIT>>>(
        poh, pol, pwprojh, pwprojl, px1, nullptr, x,
        nullptr, nullptr, nullptr, BT_, D_, D_, D_, D_, 0);
    // fused ln2 + router (out = ln2(x1), also fp16 copy for moe1)
    ln2_router_kernel<<<BT_, 256>>>(px1, ln2_w, out, px2h, router_w, pcnt, pasn, pwt);
    // moe1: hid = gelu(x2 @ w1^T)
    tgemm<1,2,false><<<dim3(FF_ / 128, BT_ / 128, E_), 256, SM_1P>>>(
        px2h, nullptr, pw1h, nullptr, phid, nullptr, nullptr,
        pcnt, pasn, nullptr, 0, D_, D_, D_, FF_, (size_t)FF_ * D_);
    // moe2: out += wt * (hid @ w2^T)  (atomic accumulate, no combine pass)
    tgemm<2,3,false><<<dim3(D_ / 128, BT_ / 128, E_), 256, SM_1P>>>(
        phid, nullptr, pw2h, nullptr, out, nullptr, nullptr,
        pcnt, pasn, pwt, 0, FF_, FF_, FF_, D_, (size_t)D_ * FF_);
}